// round 7
// baseline (speedup 1.0000x reference)
#include <cuda_runtime.h>
#include <cuda_bf16.h>
#include <math.h>
#include <stdint.h>

#define N_SEQ   256
#define T_LEN   128
#define EMBED   512
#define UNITS   512
#define GATEC   2048
#define M_ALL   (N_SEQ * T_LEN)
#define REC_CTAS 128

// dynamic smem layout for rec kernel
// B (U tiles):  [prec2][kc8][64 rows][128B swizzled] = 131072 B at offset 0
// A (h tiles):  2 bufs x [prec2][128 rows][128B swizzled] = 65536 B
#define SM_B     0
#define SM_A     131072
#define SMEM_REC (SM_A + 65536)          // 196608 B

#define SWZ(o) ((o) ^ (((o) >> 3) & 0x70))

// ---------------- PTX helpers (all plain-sm_103-legal) ----------------------
__device__ __forceinline__ uint32_t s2u(const void* p) {
    uint32_t a;
    asm("{ .reg .u64 t; cvta.to.shared.u64 t, %1; cvt.u32.u64 %0, t; }"
        : "=r"(a) : "l"(p));
    return a;
}
__device__ __forceinline__ void cpasync16(uint32_t dst, const void* src) {
    asm volatile("cp.async.cg.shared.global [%0], [%1], 16;" :: "r"(dst), "l"(src));
}
__device__ __forceinline__ void cpcommit() { asm volatile("cp.async.commit_group;"); }
template <int N> __device__ __forceinline__ void cpwait() {
    asm volatile("cp.async.wait_group %0;" :: "n"(N));
}
__device__ __forceinline__ void ldsm4(uint32_t* r, uint32_t addr) {
    asm volatile("ldmatrix.sync.aligned.m8n8.x4.shared.b16 {%0,%1,%2,%3}, [%4];"
        : "=r"(r[0]), "=r"(r[1]), "=r"(r[2]), "=r"(r[3]) : "r"(addr));
}
__device__ __forceinline__ void mma16816(float* c, const uint32_t* a, const uint32_t* b) {
    asm volatile(
        "mma.sync.aligned.m16n8k16.row.col.f32.bf16.bf16.f32 "
        "{%0,%1,%2,%3}, {%4,%5,%6,%7}, {%8,%9}, {%0,%1,%2,%3};"
        : "+f"(c[0]), "+f"(c[1]), "+f"(c[2]), "+f"(c[3])
        : "r"(a[0]), "r"(a[1]), "r"(a[2]), "r"(a[3]), "r"(b[0]), "r"(b[1]));
}

// A fragment (m16 x k16, row-major), rows mb..mb+15, k-bytes kb within 128B rows
__device__ __forceinline__ void ldA16(uint32_t* r, uint32_t tile, int mb, int kb, int lane) {
    uint32_t o = (uint32_t)((mb + (lane & 15)) * 128 + kb + ((lane >> 4) << 4));
    ldsm4(r, tile + SWZ(o));
}
// B fragments for two n8 tiles (rows nb..nb+15 of [n][k] layout)
__device__ __forceinline__ void ldB16(uint32_t* r, uint32_t tile, int nb, int kb, int lane) {
    uint32_t o = (uint32_t)((nb + ((lane >> 4) << 3) + (lane & 7)) * 128 + kb
                            + (((lane >> 3) & 1) << 4));
    ldsm4(r, tile + SWZ(o));
}

// ---------------- scratch ---------------------------------------------------
__device__ float          g_xW[2][M_ALL][GATEC];        // permuted-column x@W + b
__device__ __nv_bfloat16  g_Upk[2][2][GATEC][UNITS];    // [prec][dir][packed n][k]
__device__ __nv_bfloat16  g_hsp[2][2][2][N_SEQ][UNITS]; // [prec][dir][parity][n][u]
__device__ unsigned       g_bar;

// packed col p (0..63): j=p>>3, q=(p>>1)&3, e=p&1 -> unit=(j>>1)*4+q, gate=(j&1)*2+e
// global packed col P = nt*64 + p, global unit = nt*16 + unit.

// ---------------- init: zero h parity 0 + barrier ---------------------------
__global__ void init_kernel()
{
    int i = blockIdx.x * 256 + threadIdx.x;
    if (i == 0) g_bar = 0;
    if (i < 2 * 2 * N_SEQ * UNITS) {
        int prec = i / (2 * N_SEQ * UNITS);
        int rem  = i % (2 * N_SEQ * UNITS);
        int dir  = rem / (N_SEQ * UNITS);
        int off  = rem % (N_SEQ * UNITS);
        (&g_hsp[prec][dir][0][0][0])[off] = __float2bfloat16(0.0f);
    }
}

// ---------------- U pack (permuted cols) + bf16 split -----------------------
__global__ void upack_kernel(const float* __restrict__ Uf, const float* __restrict__ Ub)
{
    int i   = blockIdx.x * 256 + threadIdx.x;   // over 2048*512
    int dir = blockIdx.y;
    if (i >= GATEC * UNITS) return;
    int P = i >> 9, k = i & 511;
    int nt = P >> 6, p = P & 63;
    int j = p >> 3, q = (p >> 1) & 3, e = p & 1;
    int unit = nt * 16 + (j >> 1) * 4 + q;
    int gate = (j & 1) * 2 + e;
    const float* U = dir ? Ub : Uf;
    float v = U[(size_t)k * GATEC + gate * UNITS + unit];
    __nv_bfloat16 hi = __float2bfloat16(v);
    __nv_bfloat16 lo = __float2bfloat16(v - __bfloat162float(hi));
    g_Upk[0][dir][P][k] = hi;
    g_Upk[1][dir][P][k] = lo;
}

// ---------------- fused embedding gather + input projection -----------------
// Same GEMM as round 3; epilogue stores into the PERMUTED column layout.
__global__ void __launch_bounds__(256, 2)
xw_kernel(const int* __restrict__ x, const float* __restrict__ emb,
          const float* __restrict__ Wf, const float* __restrict__ bf,
          const float* __restrict__ Wb, const float* __restrict__ bb)
{
    const int nt  = blockIdx.x;
    const int mt  = blockIdx.y;
    const int dir = blockIdx.z;
    const float* __restrict__ W    = dir ? Wb : Wf;
    const float* __restrict__ bias = dir ? bb : bf;
    const int m0 = mt * 128;
    const int n0 = nt * 64;

    __shared__ float sa[32][132];
    __shared__ float sb[32][64];
    __shared__ int   sid[128];

    const int tid = threadIdx.x;
    if (tid < 128) sid[tid] = x[m0 + tid];
    __syncthreads();

    const int arow = tid & 127;
    const int aseg = (tid >> 7) * 16;
    const size_t aoff = (size_t)sid[arow] * EMBED + aseg;
    const int rg = (tid >> 4) * 8;
    const int cg = (tid & 15) * 4;

    float acc[8][4];
#pragma unroll
    for (int r = 0; r < 8; r++)
#pragma unroll
        for (int c = 0; c < 4; c++) acc[r][c] = 0.0f;

    for (int k0 = 0; k0 < EMBED; k0 += 32) {
#pragma unroll
        for (int i = 0; i < 4; i++) {
            float4 v = *(const float4*)(emb + aoff + k0 + i * 4);
            int kk = aseg + i * 4;
            sa[kk + 0][arow] = v.x;
            sa[kk + 1][arow] = v.y;
            sa[kk + 2][arow] = v.z;
            sa[kk + 3][arow] = v.w;
        }
#pragma unroll
        for (int j = 0; j < 2; j++) {
            int idx = tid * 2 + j;
            int kk  = idx >> 4;
            int cc  = (idx & 15) * 4;
            *(float4*)&sb[kk][cc] =
                *(const float4*)(W + (size_t)(k0 + kk) * GATEC + n0 + cc);
        }
        __syncthreads();
#pragma unroll 16
        for (int k = 0; k < 32; k++) {
            const float4 b4 = *(const float4*)&sb[k][cg];
            const float4 x0 = *(const float4*)&sa[k][rg];
            const float4 x1 = *(const float4*)&sa[k][rg + 4];
            const float av[8] = {x0.x, x0.y, x0.z, x0.w, x1.x, x1.y, x1.z, x1.w};
#pragma unroll
            for (int r = 0; r < 8; r++) {
                acc[r][0] = fmaf(av[r], b4.x, acc[r][0]);
                acc[r][1] = fmaf(av[r], b4.y, acc[r][1]);
                acc[r][2] = fmaf(av[r], b4.z, acc[r][2]);
                acc[r][3] = fmaf(av[r], b4.w, acc[r][3]);
            }
        }
        __syncthreads();
    }

    // permuted scatter store: col (gate-major) -> packed P
    const int   gate  = n0 >> 9;            // constant per CTA (64 | 512)
    const int   ubase = (n0 & 511) + cg;
    const float4 bsv = *(const float4*)(bias + n0 + cg);
    const float bs[4] = {bsv.x, bsv.y, bsv.z, bsv.w};
#pragma unroll
    for (int r = 0; r < 8; r++) {
        const int row = m0 + rg + r;
#pragma unroll
        for (int c = 0; c < 4; c++) {
            int unit = ubase + c;
            int P = (unit >> 4) * 64
                  + (((unit >> 2) & 3) * 2 + (gate >> 1)) * 8
                  + (unit & 3) * 2 + (gate & 1);
            g_xW[dir][row][P] = acc[r][c] + bs[c];
        }
    }
}

// ---------------- persistent HMMA recurrence --------------------------------
__device__ __forceinline__ float sigmoidf_(float v) { return 1.0f / (1.0f + expf(-v)); }

__global__ void __launch_bounds__(128, 1)
rec_kernel(const int* __restrict__ x, float* __restrict__ out)
{
    extern __shared__ __align__(1024) char smem[];
    const uint32_t sb = s2u(smem);

    const int tid  = threadIdx.x;
    const int wid  = tid >> 5;
    const int lane = tid & 31;
    const int bid  = blockIdx.x;
    const int dir  = bid >> 6;
    const int mt   = (bid >> 5) & 1;
    const int nt   = bid & 31;
    const int m0   = mt * 128;
    const int wb   = wid * 32;

    // ---- one-time B (U) preload: both precisions, 8 K-chunks ---------------
    for (int i = tid; i < 8192; i += 128) {
        int prec = i >> 12;
        int kc   = (i >> 9) & 7;
        int P    = (i >> 3) & 63;
        int seg  = i & 7;
        const void* src = &g_Upk[prec][dir][nt * 64 + P][kc * 64 + seg * 8];
        uint32_t dst = sb + SM_B + (uint32_t)(prec * 8 + kc) * 8192
                     + SWZ((uint32_t)(P * 128 + seg * 16));
        cpasync16(dst, src);
    }
    cpcommit();

    // ---- persistent state ---------------------------------------------------
    float c_reg[16], h_reg[16];
#pragma unroll
    for (int s = 0; s < 16; s++) { c_reg[s] = 0.0f; h_reg[s] = 0.0f; }
    unsigned barcnt = 0;

    auto fillA = [&](int b, int kc, int pin) {
#pragma unroll
        for (int j = 0; j < 16; j++) {
            int i    = tid + j * 128;
            int prec = i >> 10;
            int r    = (i >> 3) & 127;
            int seg  = i & 7;
            const void* src = &g_hsp[prec][dir][pin][m0 + r][kc * 64 + seg * 8];
            uint32_t dst = sb + SM_A + (uint32_t)b * 32768 + (uint32_t)prec * 16384
                         + SWZ((uint32_t)(r * 128 + seg * 16));
            cpasync16(dst, src);
        }
        cpcommit();
    };

    auto gbar = [&]() {
        __threadfence();
        __syncthreads();
        barcnt++;
        if (tid == 0) {
            atomicAdd(&g_bar, 1u);
            const unsigned target = barcnt * REC_CTAS;
            while (*(volatile unsigned*)&g_bar < target) __nanosleep(64);
        }
        __syncthreads();
        __threadfence();
    };

    for (int t = 0; t < T_LEN; t++) {
        const int pin  = t & 1;
        const int pout = pin ^ 1;
        const int tt   = dir ? (T_LEN - 1 - t) : t;

        float acc[2][8][4];
#pragma unroll
        for (int a = 0; a < 2; a++)
#pragma unroll
            for (int j = 0; j < 8; j++)
#pragma unroll
                for (int c = 0; c < 4; c++) acc[a][j][c] = 0.0f;

        fillA(0, 0, pin);
        fillA(1, 1, pin);

        for (int kc = 0; kc < 8; kc++) {
            const int b = kc & 1;
            if (kc < 7) cpwait<1>(); else cpwait<0>();
            __syncthreads();

            const uint32_t aHi = sb + SM_A + (uint32_t)b * 32768;
            const uint32_t aLo = aHi + 16384;
            const uint32_t bHi = sb + SM_B + (uint32_t)kc * 8192;
            const uint32_t bLo = bHi + 65536u;

#pragma unroll
            for (int kk = 0; kk < 4; kk++) {
                const int kb = kk * 32;
                uint32_t af[2][4], bfr[4][4];

                // pass 1: hi * hi
                ldA16(af[0], aHi, wb,      kb, lane);
                ldA16(af[1], aHi, wb + 16, kb, lane);
#pragma unroll
                for (int p4 = 0; p4 < 4; p4++) ldB16(bfr[p4], bHi, p4 * 16, kb, lane);
#pragma unroll
                for (int a = 0; a < 2; a++)
#pragma unroll
                    for (int j = 0; j < 8; j++)
                        mma16816(acc[a][j], af[a], &bfr[j >> 1][(j & 1) * 2]);

                // pass 2: hi * lo
#pragma unroll
                for (int p4 = 0; p4 < 4; p4++) ldB16(bfr[p4], bLo, p4 * 16, kb, lane);
#pragma unroll
                for (int a = 0; a < 2; a++)
#pragma unroll
                    for (int j = 0; j < 8; j++)
                        mma16816(acc[a][j], af[a], &bfr[j >> 1][(j & 1) * 2]);

                // pass 3: lo * hi
                ldA16(af[0], aLo, wb,      kb, lane);
                ldA16(af[1], aLo, wb + 16, kb, lane);
#pragma unroll
                for (int p4 = 0; p4 < 4; p4++) ldB16(bfr[p4], bHi, p4 * 16, kb, lane);
#pragma unroll
                for (int a = 0; a < 2; a++)
#pragma unroll
                    for (int j = 0; j < 8; j++)
                        mma16816(acc[a][j], af[a], &bfr[j >> 1][(j & 1) * 2]);
            }

            __syncthreads();                     // all warps done with buf b
            if (kc + 2 <= 7) fillA(b, kc + 2, pin);
        }

        // ---- gate math + masked update; lane owns 4 rows x 4 units ---------
#pragma unroll
        for (int rr = 0; rr < 4; rr++) {
            const int rloc = wb + (rr >> 1) * 16 + (rr & 1) * 8 + (lane >> 2);
            const int n    = m0 + rloc;
            const int rowi = n * T_LEN + tt;
            const bool msk = (x[rowi] != 0);
            const float* xwp = &g_xW[dir][rowi][nt * 64];
#pragma unroll
            for (int uu = 0; uu < 4; uu++) {
                float z[4];
#pragma unroll
                for (int jl = 0; jl < 2; jl++) {
                    const int j = uu * 2 + jl;
                    float2 v = *(const float2*)(xwp + j * 8 + (lane & 3) * 2);
                    z[jl * 2 + 0] = v.x + acc[rr >> 1][j][(rr & 1) * 2 + 0];
                    z[jl * 2 + 1] = v.y + acc[rr >> 1][j][(rr & 1) * 2 + 1];
                }
                const int s = rr * 4 + uu;
                float ig = sigmoidf_(z[0]), fg = sigmoidf_(z[1]);
                float gg = tanhf(z[2]),     og = sigmoidf_(z[3]);
                float cn = fmaf(fg, c_reg[s], ig * gg);
                float hn = og * tanhf(cn);
                if (!msk) { cn = c_reg[s]; hn = h_reg[s]; }
                c_reg[s] = cn;
                h_reg[s] = hn;
                const int gu = nt * 16 + uu * 4 + (lane & 3);
                __nv_bfloat16 hh = __float2bfloat16(hn);
                g_hsp[0][dir][pout][n][gu] = hh;
                g_hsp[1][dir][pout][n][gu] = __float2bfloat16(hn - __bfloat162float(hh));
            }
        }

        if (t < T_LEN - 1) gbar();
    }

    // ---- final output: concat(h_fwd, h_bwd), straight from registers -------
#pragma unroll
    for (int rr = 0; rr < 4; rr++) {
        const int n = m0 + wb + (rr >> 1) * 16 + (rr & 1) * 8 + (lane >> 2);
#pragma unroll
        for (int uu = 0; uu < 4; uu++) {
            const int gu = nt * 16 + uu * 4 + (lane & 3);
            out[(size_t)n * 1024 + dir * 512 + gu] = h_reg[rr * 4 + uu];
        }
    }
}

// ---------------- launch ----------------------------------------------------
extern "C" void kernel_launch(void* const* d_in, const int* in_sizes, int n_in,
                              void* d_out, int out_size)
{
    const int*   x   = (const int*)  d_in[0];
    const float* emb = (const float*)d_in[1];
    const float* Wf  = (const float*)d_in[2];
    const float* Uf  = (const float*)d_in[3];
    const float* bf  = (const float*)d_in[4];
    const float* Wb  = (const float*)d_in[5];
    const float* Ub  = (const float*)d_in[6];
    const float* bb  = (const float*)d_in[7];
    float* out = (float*)d_out;
    (void)in_sizes; (void)n_in; (void)out_size;

    cudaFuncSetAttribute(rec_kernel,
                         cudaFuncAttributeMaxDynamicSharedMemorySize, SMEM_REC);

    init_kernel<<<2048, 256>>>();
    upack_kernel<<<dim3(4096, 2), 256>>>(Uf, Ub);

    dim3 gx(32, 256, 2);
    xw_kernel<<<gx, 256>>>(x, emb, Wf, bf, Wb, bb);

    rec_kernel<<<REC_CTAS, 128, SMEM_REC>>>(x, out);
}

// round 8
// speedup vs baseline: 1.2228x; 1.2228x over previous
#include <cuda_runtime.h>
#include <cuda_bf16.h>
#include <math.h>
#include <stdint.h>

#define N_SEQ   256
#define T_LEN   128
#define EMBED   512
#define UNITS   512
#define GATEC   2048
#define M_ALL   (N_SEQ * T_LEN)

// rec kernel smem: B (U tiles) 128KB + A (h tiles) 3 x 32KB = 224KB
#define SM_B     0
#define SM_A     131072
#define SMEM_REC (SM_A + 3 * 32768)      // 229376 B

#define SWZ(o) ((o) ^ (((o) >> 3) & 0x70))

// ---------------- PTX helpers (plain-sm_103-legal only) ---------------------
__device__ __forceinline__ uint32_t s2u(const void* p) {
    uint32_t a;
    asm("{ .reg .u64 t; cvta.to.shared.u64 t, %1; cvt.u32.u64 %0, t; }"
        : "=r"(a) : "l"(p));
    return a;
}
__device__ __forceinline__ void cpasync16(uint32_t dst, const void* src) {
    asm volatile("cp.async.cg.shared.global [%0], [%1], 16;" :: "r"(dst), "l"(src));
}
__device__ __forceinline__ void cpcommit() { asm volatile("cp.async.commit_group;"); }
template <int N> __device__ __forceinline__ void cpwait() {
    asm volatile("cp.async.wait_group %0;" :: "n"(N));
}
__device__ __forceinline__ void ldsm4(uint32_t* r, uint32_t addr) {
    asm volatile("ldmatrix.sync.aligned.m8n8.x4.shared.b16 {%0,%1,%2,%3}, [%4];"
        : "=r"(r[0]), "=r"(r[1]), "=r"(r[2]), "=r"(r[3]) : "r"(addr));
}
__device__ __forceinline__ void mma16816(float* c, const uint32_t* a, const uint32_t* b) {
    asm volatile(
        "mma.sync.aligned.m16n8k16.row.col.f32.bf16.bf16.f32 "
        "{%0,%1,%2,%3}, {%4,%5,%6,%7}, {%8,%9}, {%0,%1,%2,%3};"
        : "+f"(c[0]), "+f"(c[1]), "+f"(c[2]), "+f"(c[3])
        : "r"(a[0]), "r"(a[1]), "r"(a[2]), "r"(a[3]), "r"(b[0]), "r"(b[1]));
}
// A fragment m16xk16 row-major: rows mb.., k-bytes kb within 128B rows
__device__ __forceinline__ void ldA16(uint32_t* r, uint32_t tile, int mb, int kb, int lane) {
    uint32_t o = (uint32_t)((mb + (lane & 15)) * 128 + kb + ((lane >> 4) << 4));
    ldsm4(r, tile + SWZ(o));
}
// B fragments: two n8 tiles (rows nb..nb+15 of [n][k] layout)
__device__ __forceinline__ void ldB16(uint32_t* r, uint32_t tile, int nb, int kb, int lane) {
    uint32_t o = (uint32_t)((nb + ((lane >> 4) << 3) + (lane & 7)) * 128 + kb
                            + (((lane >> 3) & 1) << 4));
    ldsm4(r, tile + SWZ(o));
}

// ---------------- scratch ---------------------------------------------------
__device__ float          g_xW[2][M_ALL][GATEC];        // natural layout x@W + b
__device__ __nv_bfloat16  g_Upk[2][2][GATEC][UNITS];    // [prec][dir][packed n][k]
__device__ __nv_bfloat16  g_hsp[2][2][2][N_SEQ][UNITS]; // [prec][dir][parity][n][u]
__device__ unsigned       g_bar4[4];                    // per-(dir,mt) group barrier

// packed col p: j=p>>3, q=(p>>1)&3, e=p&1 -> unit=(j>>1)*4+q, gate=(j&1)*2+e

// ---------------- init ------------------------------------------------------
__global__ void init_kernel()
{
    int i = blockIdx.x * 256 + threadIdx.x;
    if (i < 4) g_bar4[i] = 0;
    if (i < 2 * 2 * N_SEQ * UNITS) {
        int prec = i / (2 * N_SEQ * UNITS);
        int rem  = i % (2 * N_SEQ * UNITS);
        int dir  = rem / (N_SEQ * UNITS);
        int off  = rem % (N_SEQ * UNITS);
        (&g_hsp[prec][dir][0][0][0])[off] = __float2bfloat16(0.0f);
    }
}

// ---------------- U pack (permuted cols) + bf16 split -----------------------
__global__ void upack_kernel(const float* __restrict__ Uf, const float* __restrict__ Ub)
{
    int i   = blockIdx.x * 256 + threadIdx.x;   // over 2048*512
    int dir = blockIdx.y;
    if (i >= GATEC * UNITS) return;
    int P = i >> 9, k = i & 511;
    int nt = P >> 6, p = P & 63;
    int j = p >> 3, q = (p >> 1) & 3, e = p & 1;
    int unit = nt * 16 + (j >> 1) * 4 + q;
    int gate = (j & 1) * 2 + e;
    const float* U = dir ? Ub : Uf;
    float v = U[(size_t)k * GATEC + gate * UNITS + unit];
    __nv_bfloat16 hi = __float2bfloat16(v);
    __nv_bfloat16 lo = __float2bfloat16(v - __bfloat162float(hi));
    g_Upk[0][dir][P][k] = hi;
    g_Upk[1][dir][P][k] = lo;
}

// ---------------- fused embedding gather + input projection (round-3) -------
__global__ void __launch_bounds__(256, 2)
xw_kernel(const int* __restrict__ x, const float* __restrict__ emb,
          const float* __restrict__ Wf, const float* __restrict__ bf,
          const float* __restrict__ Wb, const float* __restrict__ bb)
{
    const int nt  = blockIdx.x;
    const int mt  = blockIdx.y;
    const int dir = blockIdx.z;
    const float* __restrict__ W    = dir ? Wb : Wf;
    const float* __restrict__ bias = dir ? bb : bf;
    const int m0 = mt * 128;
    const int n0 = nt * 64;

    __shared__ float sa[32][132];
    __shared__ float sb[32][64];
    __shared__ int   sid[128];

    const int tid = threadIdx.x;
    if (tid < 128) sid[tid] = x[m0 + tid];
    __syncthreads();

    const int arow = tid & 127;
    const int aseg = (tid >> 7) * 16;
    const size_t aoff = (size_t)sid[arow] * EMBED + aseg;
    const int rg = (tid >> 4) * 8;
    const int cg = (tid & 15) * 4;

    float acc[8][4];
#pragma unroll
    for (int r = 0; r < 8; r++)
#pragma unroll
        for (int c = 0; c < 4; c++) acc[r][c] = 0.0f;

    for (int k0 = 0; k0 < EMBED; k0 += 32) {
#pragma unroll
        for (int i = 0; i < 4; i++) {
            float4 v = *(const float4*)(emb + aoff + k0 + i * 4);
            int kk = aseg + i * 4;
            sa[kk + 0][arow] = v.x;
            sa[kk + 1][arow] = v.y;
            sa[kk + 2][arow] = v.z;
            sa[kk + 3][arow] = v.w;
        }
#pragma unroll
        for (int j = 0; j < 2; j++) {
            int idx = tid * 2 + j;
            int kk  = idx >> 4;
            int cc  = (idx & 15) * 4;
            *(float4*)&sb[kk][cc] =
                *(const float4*)(W + (size_t)(k0 + kk) * GATEC + n0 + cc);
        }
        __syncthreads();
#pragma unroll 16
        for (int k = 0; k < 32; k++) {
            const float4 b4 = *(const float4*)&sb[k][cg];
            const float4 x0 = *(const float4*)&sa[k][rg];
            const float4 x1 = *(const float4*)&sa[k][rg + 4];
            const float av[8] = {x0.x, x0.y, x0.z, x0.w, x1.x, x1.y, x1.z, x1.w};
#pragma unroll
            for (int r = 0; r < 8; r++) {
                acc[r][0] = fmaf(av[r], b4.x, acc[r][0]);
                acc[r][1] = fmaf(av[r], b4.y, acc[r][1]);
                acc[r][2] = fmaf(av[r], b4.z, acc[r][2]);
                acc[r][3] = fmaf(av[r], b4.w, acc[r][3]);
            }
        }
        __syncthreads();
    }

    const float4 bsv = *(const float4*)(bias + n0 + cg);
#pragma unroll
    for (int r = 0; r < 8; r++) {
        const int row = m0 + rg + r;
        float4 o;
        o.x = acc[r][0] + bsv.x;
        o.y = acc[r][1] + bsv.y;
        o.z = acc[r][2] + bsv.z;
        o.w = acc[r][3] + bsv.w;
        *(float4*)&g_xW[dir][row][n0 + cg] = o;
    }
}

// ---------------- persistent HMMA recurrence (8 warps/CTA) ------------------
__device__ __forceinline__ float sigmoidf_(float v) { return 1.0f / (1.0f + expf(-v)); }

__global__ void __launch_bounds__(256, 1)
rec_kernel(const int* __restrict__ x, float* __restrict__ out)
{
    extern __shared__ __align__(1024) char smem[];
    const uint32_t sb = s2u(smem);

    const int tid  = threadIdx.x;
    const int wid  = tid >> 5;
    const int lane = tid & 31;
    const int bid  = blockIdx.x;
    const int dir  = bid >> 6;
    const int mt   = (bid >> 5) & 1;
    const int nt   = bid & 31;
    const int grp  = bid >> 5;             // (dir,mt) group of 32 CTAs
    const int m0   = mt * 128;
    const int wb   = wid * 16;             // warp's 16-row M tile

    // ---- one-time B (U) preload: both precisions, 8 K-chunks ---------------
    for (int i = tid; i < 8192; i += 256) {
        int prec = i >> 12;
        int kc   = (i >> 9) & 7;
        int P    = (i >> 3) & 63;
        int seg  = i & 7;
        const void* src = &g_Upk[prec][dir][nt * 64 + P][kc * 64 + seg * 8];
        uint32_t dst = sb + SM_B + (uint32_t)(prec * 8 + kc) * 8192
                     + SWZ((uint32_t)(P * 128 + seg * 16));
        cpasync16(dst, src);
    }
    cpcommit();

    float c_reg[8], h_reg[8];
#pragma unroll
    for (int s = 0; s < 8; s++) { c_reg[s] = 0.0f; h_reg[s] = 0.0f; }
    unsigned barcnt = 0;

    auto fillA = [&](int b, int kc, int pin) {
#pragma unroll
        for (int j = 0; j < 8; j++) {
            int i    = tid + j * 256;
            int prec = i >> 10;
            int r    = (i >> 3) & 127;
            int seg  = i & 7;
            const void* src = &g_hsp[prec][dir][pin][m0 + r][kc * 64 + seg * 8];
            uint32_t dst = sb + SM_A + (uint32_t)b * 32768 + (uint32_t)prec * 16384
                         + SWZ((uint32_t)(r * 128 + seg * 16));
            cpasync16(dst, src);
        }
        cpcommit();
    };

    auto gbar = [&]() {
        __threadfence();
        __syncthreads();
        barcnt++;
        if (tid == 0) {
            atomicAdd(&g_bar4[grp], 1u);
            const unsigned target = barcnt * 32;
            while (*(volatile unsigned*)&g_bar4[grp] < target) __nanosleep(32);
        }
        __syncthreads();
        __threadfence();
    };

    const int rA = lane >> 2;              // row within 8-row half
    const int cq = lane & 3;               // quad col

    for (int t = 0; t < T_LEN; t++) {
        const int pin  = t & 1;
        const int pout = pin ^ 1;
        const int tt   = dir ? (T_LEN - 1 - t) : t;

        // prefetch mask + xW (natural layout, permutation applied here)
        const int n0r   = m0 + wb + rA;
        const int row0  = n0r * T_LEN + tt;
        const int row1  = (n0r + 8) * T_LEN + tt;
        const int msk0  = x[row0];
        const int msk1  = x[row1];
        float xwv[2][4][4];
#pragma unroll
        for (int rh = 0; rh < 2; rh++) {
            const float* base = &g_xW[dir][rh ? row1 : row0][nt * 16 + cq];
#pragma unroll
            for (int uu = 0; uu < 4; uu++)
#pragma unroll
                for (int g = 0; g < 4; g++)
                    xwv[rh][uu][g] = base[g * UNITS + uu * 4];
        }

        float acc[8][4];
#pragma unroll
        for (int j = 0; j < 8; j++)
#pragma unroll
            for (int c = 0; c < 4; c++) acc[j][c] = 0.0f;

        fillA(0, 0, pin);
        fillA(1, 1, pin);
        fillA(2, 2, pin);

        for (int kc = 0; kc < 8; kc++) {
            if (kc < 6) cpwait<2>();
            else if (kc == 6) cpwait<1>();
            else cpwait<0>();
            __syncthreads();

            const uint32_t aHi = sb + SM_A + (uint32_t)(kc % 3) * 32768;
            const uint32_t aLo = aHi + 16384;
            const uint32_t bHi = sb + SM_B + (uint32_t)kc * 8192;
            const uint32_t bLo = bHi + 65536u;

#pragma unroll
            for (int kk = 0; kk < 4; kk++) {
                const int kb = kk * 32;
                uint32_t afh[4], afl[4], bh[4][4], bl[4][4];
                ldA16(afh, aHi, wb, kb, lane);
                ldA16(afl, aLo, wb, kb, lane);
#pragma unroll
                for (int p4 = 0; p4 < 4; p4++) {
                    ldB16(bh[p4], bHi, p4 * 16, kb, lane);
                    ldB16(bl[p4], bLo, p4 * 16, kb, lane);
                }
#pragma unroll
                for (int j = 0; j < 8; j++)
                    mma16816(acc[j], afh, &bh[j >> 1][(j & 1) * 2]);
#pragma unroll
                for (int j = 0; j < 8; j++)
                    mma16816(acc[j], afh, &bl[j >> 1][(j & 1) * 2]);
#pragma unroll
                for (int j = 0; j < 8; j++)
                    mma16816(acc[j], afl, &bh[j >> 1][(j & 1) * 2]);
            }

            __syncthreads();
            if (kc + 3 < 8) fillA(kc % 3, kc + 3, pin);
        }

        // ---- gate math + masked update; lane owns 2 rows x 4 units ---------
#pragma unroll
        for (int rh = 0; rh < 2; rh++) {
            const int n    = n0r + rh * 8;
            const bool msk = (rh ? msk1 : msk0) != 0;
#pragma unroll
            for (int uu = 0; uu < 4; uu++) {
                const float zi = xwv[rh][uu][0] + acc[uu * 2 + 0][rh * 2 + 0];
                const float zf = xwv[rh][uu][1] + acc[uu * 2 + 0][rh * 2 + 1];
                const float zg = xwv[rh][uu][2] + acc[uu * 2 + 1][rh * 2 + 0];
                const float zo = xwv[rh][uu][3] + acc[uu * 2 + 1][rh * 2 + 1];
                const int s = rh * 4 + uu;
                float ig = sigmoidf_(zi), fg = sigmoidf_(zf);
                float gg = tanhf(zg),     og = sigmoidf_(zo);
                float cn = fmaf(fg, c_reg[s], ig * gg);
                float hn = og * tanhf(cn);
                if (!msk) { cn = c_reg[s]; hn = h_reg[s]; }
                c_reg[s] = cn;
                h_reg[s] = hn;
                const int gu = nt * 16 + uu * 4 + cq;
                __nv_bfloat16 hh = __float2bfloat16(hn);
                g_hsp[0][dir][pout][n][gu] = hh;
                g_hsp[1][dir][pout][n][gu] = __float2bfloat16(hn - __bfloat162float(hh));
            }
        }

        if (t < T_LEN - 1) gbar();
    }

    // ---- final output: concat(h_fwd, h_bwd), straight from registers -------
#pragma unroll
    for (int rh = 0; rh < 2; rh++) {
        const int n = m0 + wb + rA + rh * 8;
#pragma unroll
        for (int uu = 0; uu < 4; uu++) {
            const int gu = nt * 16 + uu * 4 + cq;
            out[(size_t)n * 1024 + dir * 512 + gu] = h_reg[rh * 4 + uu];
        }
    }
}

// ---------------- launch ----------------------------------------------------
extern "C" void kernel_launch(void* const* d_in, const int* in_sizes, int n_in,
                              void* d_out, int out_size)
{
    const int*   x   = (const int*)  d_in[0];
    const float* emb = (const float*)d_in[1];
    const float* Wf  = (const float*)d_in[2];
    const float* Uf  = (const float*)d_in[3];
    const float* bf  = (const float*)d_in[4];
    const float* Wb  = (const float*)d_in[5];
    const float* Ub  = (const float*)d_in[6];
    const float* bb  = (const float*)d_in[7];
    float* out = (float*)d_out;
    (void)in_sizes; (void)n_in; (void)out_size;

    cudaFuncSetAttribute(rec_kernel,
                         cudaFuncAttributeMaxDynamicSharedMemorySize, SMEM_REC);

    init_kernel<<<2048, 256>>>();
    upack_kernel<<<dim3(4096, 2), 256>>>(Uf, Ub);

    dim3 gx(32, 256, 2);
    xw_kernel<<<gx, 256>>>(x, emb, Wf, bf, Wb, bb);

    rec_kernel<<<128, 256, SMEM_REC>>>(x, out);
}

// round 10
// speedup vs baseline: 3.4250x; 2.8011x over previous
#include <cuda_runtime.h>
#include <cuda_bf16.h>
#include <math.h>
#include <stdint.h>

#define N_SEQ   256
#define T_LEN   128
#define EMBED   512
#define UNITS   512
#define GATEC   2048
#define M_ALL   (N_SEQ * T_LEN)

// rec kernel smem: B (U tiles) 128KB + A (h tiles) 3 x 32KB
#define SM_B     0
#define SM_A     131072
#define SMEM_REC (SM_A + 3 * 32768)      // 229376 B
// xw kernel smem: 2 bufs x (A 32KB + B 32KB)
#define SMEM_XW  131072

#define SWZ(o) ((o) ^ (((o) >> 3) & 0x70))

// ---------------- PTX helpers (plain-sm_103-legal only) ---------------------
__device__ __forceinline__ uint32_t s2u(const void* p) {
    uint32_t a;
    asm("{ .reg .u64 t; cvta.to.shared.u64 t, %1; cvt.u32.u64 %0, t; }"
        : "=r"(a) : "l"(p));
    return a;
}
__device__ __forceinline__ void cpasync16(uint32_t dst, const void* src) {
    asm volatile("cp.async.cg.shared.global [%0], [%1], 16;" :: "r"(dst), "l"(src));
}
__device__ __forceinline__ void cpcommit() { asm volatile("cp.async.commit_group;"); }
template <int N> __device__ __forceinline__ void cpwait() {
    asm volatile("cp.async.wait_group %0;" :: "n"(N));
}
__device__ __forceinline__ void ldsm4(uint32_t* r, uint32_t addr) {
    asm volatile("ldmatrix.sync.aligned.m8n8.x4.shared.b16 {%0,%1,%2,%3}, [%4];"
        : "=r"(r[0]), "=r"(r[1]), "=r"(r[2]), "=r"(r[3]) : "r"(addr));
}
__device__ __forceinline__ void mma16816(float* c, const uint32_t* a, const uint32_t* b) {
    asm volatile(
        "mma.sync.aligned.m16n8k16.row.col.f32.bf16.bf16.f32 "
        "{%0,%1,%2,%3}, {%4,%5,%6,%7}, {%8,%9}, {%0,%1,%2,%3};"
        : "+f"(c[0]), "+f"(c[1]), "+f"(c[2]), "+f"(c[3])
        : "r"(a[0]), "r"(a[1]), "r"(a[2]), "r"(a[3]), "r"(b[0]), "r"(b[1]));
}
// A fragment m16xk16 row-major: rows mb.., k-bytes kb within 128B rows
__device__ __forceinline__ void ldA16(uint32_t* r, uint32_t tile, int mb, int kb, int lane) {
    uint32_t o = (uint32_t)((mb + (lane & 15)) * 128 + kb + ((lane >> 4) << 4));
    ldsm4(r, tile + SWZ(o));
}
// B fragments: two n8 tiles (rows nb..nb+15 of [n][k] layout)
__device__ __forceinline__ void ldB16(uint32_t* r, uint32_t tile, int nb, int kb, int lane) {
    uint32_t o = (uint32_t)((nb + ((lane >> 4) << 3) + (lane & 7)) * 128 + kb
                            + (((lane >> 3) & 1) << 4));
    ldsm4(r, tile + SWZ(o));
}

// ---------------- scratch ---------------------------------------------------
__device__ float          g_xW[2][M_ALL][GATEC];        // natural layout x@W + b
__device__ __nv_bfloat16  g_Upk[2][2][GATEC][UNITS];    // rec U [prec][dir][packed n][k]
__device__ __nv_bfloat16  g_Wpk[2][2][GATEC][EMBED];    // xw W [prec][dir][n][k]
__device__ __nv_bfloat16  g_Asp[2][M_ALL][EMBED];       // gathered emb split [prec][m][k]
__device__ __nv_bfloat16  g_hsp[2][2][2][N_SEQ][UNITS]; // [prec][dir][parity][n][u]
__device__ unsigned       g_bar4[4];                    // per-(dir,mt) group barrier

// ---------------- init ------------------------------------------------------
__global__ void init_kernel()
{
    int i = blockIdx.x * 256 + threadIdx.x;
    if (i < 4) g_bar4[i] = 0;
    if (i < 2 * 2 * N_SEQ * UNITS) {
        int prec = i / (2 * N_SEQ * UNITS);
        int rem  = i % (2 * N_SEQ * UNITS);
        int dir  = rem / (N_SEQ * UNITS);
        int off  = rem % (N_SEQ * UNITS);
        (&g_hsp[prec][dir][0][0][0])[off] = __float2bfloat16(0.0f);
    }
}

// ---------------- U pack (permuted cols) + bf16 split (rec, unchanged) ------
__global__ void upack_kernel(const float* __restrict__ Uf, const float* __restrict__ Ub)
{
    int i   = blockIdx.x * 256 + threadIdx.x;
    int dir = blockIdx.y;
    if (i >= GATEC * UNITS) return;
    int P = i >> 9, k = i & 511;
    int nt = P >> 6, p = P & 63;
    int j = p >> 3, q = (p >> 1) & 3, e = p & 1;
    int unit = nt * 16 + (j >> 1) * 4 + q;
    int gate = (j & 1) * 2 + e;
    const float* U = dir ? Ub : Uf;
    float v = U[(size_t)k * GATEC + gate * UNITS + unit];
    __nv_bfloat16 hi = __float2bfloat16(v);
    __nv_bfloat16 lo = __float2bfloat16(v - __bfloat162float(hi));
    g_Upk[0][dir][P][k] = hi;
    g_Upk[1][dir][P][k] = lo;
}

// ---------------- W pack: [k][n] fp32 -> [n][k] bf16 hi/lo ------------------
__global__ void wpack_kernel(const float* __restrict__ Wf, const float* __restrict__ Wb)
{
    int i   = blockIdx.x * 256 + threadIdx.x;   // over 2048*512
    int dir = blockIdx.y;
    if (i >= GATEC * EMBED) return;
    int n = i >> 9, k = i & 511;
    const float* W = dir ? Wb : Wf;
    float v = W[(size_t)k * GATEC + n];
    __nv_bfloat16 hi = __float2bfloat16(v);
    __nv_bfloat16 lo = __float2bfloat16(v - __bfloat162float(hi));
    g_Wpk[0][dir][n][k] = hi;
    g_Wpk[1][dir][n][k] = lo;
}

// ---------------- A pack: gather emb rows, split bf16 -----------------------
__global__ void apack_kernel(const int* __restrict__ x, const float* __restrict__ emb)
{
    const int m  = blockIdx.x;                  // 0..32767
    const int k2 = threadIdx.x;                 // 0..255 (pairs)
    const int id = x[m];
    float2 v = *(const float2*)(emb + (size_t)id * EMBED + k2 * 2);
    __nv_bfloat16 hx = __float2bfloat16(v.x);
    __nv_bfloat16 hy = __float2bfloat16(v.y);
    __nv_bfloat162 hi, lo;
    hi.x = hx; hi.y = hy;
    lo.x = __float2bfloat16(v.x - __bfloat162float(hx));
    lo.y = __float2bfloat16(v.y - __bfloat162float(hy));
    *(__nv_bfloat162*)&g_Asp[0][m][k2 * 2] = hi;
    *(__nv_bfloat162*)&g_Asp[1][m][k2 * 2] = lo;
}

// ---------------- input projection via HMMA split-bf16 ----------------------
__global__ void __launch_bounds__(256, 1)
xw_hmma(const float* __restrict__ bf_, const float* __restrict__ bb_)
{
    extern __shared__ __align__(1024) char smem[];
    const uint32_t sb = s2u(smem);

    const int tid  = threadIdx.x;
    const int wid  = tid >> 5;
    const int lane = tid & 31;
    const int nt   = blockIdx.x;               // 0..15 (128-col N tiles)
    const int mt   = blockIdx.y;               // 0..255
    const int dir  = blockIdx.z;
    const int m0   = mt * 128;
    const int n0   = nt * 128;
    const float* __restrict__ bias = dir ? bb_ : bf_;

    const int mg = wid & 3;                    // warp m-group (32 rows)
    const int ng = wid >> 2;                   // warp n-group (64 cols)

    auto fill = [&](int b, int kc) {
#pragma unroll
        for (int j = 0; j < 16; j++) {
            int i    = tid + j * 256;          // 0..4095
            int reg  = i >> 10;                // 0:Ahi 1:Alo 2:Bhi 3:Blo
            int idx  = i & 1023;
            int r    = idx >> 3;
            int seg  = idx & 7;
            const void* src = (reg < 2)
                ? (const void*)&g_Asp[reg][m0 + r][kc * 64 + seg * 8]
                : (const void*)&g_Wpk[reg - 2][dir][n0 + r][kc * 64 + seg * 8];
            uint32_t dst = sb + (uint32_t)b * 65536 + (uint32_t)reg * 16384
                         + SWZ((uint32_t)(r * 128 + seg * 16));
            cpasync16(dst, src);
        }
        cpcommit();
    };

    float acc[2][8][4];
#pragma unroll
    for (int a = 0; a < 2; a++)
#pragma unroll
        for (int j = 0; j < 8; j++)
#pragma unroll
            for (int c = 0; c < 4; c++) acc[a][j][c] = 0.0f;

    fill(0, 0);
    fill(1, 1);

    for (int kc = 0; kc < 8; kc++) {
        const int b = kc & 1;
        if (kc < 7) cpwait<1>(); else cpwait<0>();
        __syncthreads();

        const uint32_t aHi = sb + (uint32_t)b * 65536;
        const uint32_t aLo = aHi + 16384;
        const uint32_t bHi = aHi + 32768;
        const uint32_t bLo = aHi + 49152;

#pragma unroll
        for (int kk = 0; kk < 4; kk++) {
            const int kb = kk * 32;
            uint32_t afh[2][4], afl[2][4], bh[4][4], bl[4][4];
            ldA16(afh[0], aHi, mg * 32,      kb, lane);
            ldA16(afh[1], aHi, mg * 32 + 16, kb, lane);
            ldA16(afl[0], aLo, mg * 32,      kb, lane);
            ldA16(afl[1], aLo, mg * 32 + 16, kb, lane);
#pragma unroll
            for (int p4 = 0; p4 < 4; p4++) {
                ldB16(bh[p4], bHi, ng * 64 + p4 * 16, kb, lane);
                ldB16(bl[p4], bLo, ng * 64 + p4 * 16, kb, lane);
            }
#pragma unroll
            for (int a = 0; a < 2; a++)
#pragma unroll
                for (int j = 0; j < 8; j++)
                    mma16816(acc[a][j], afh[a], &bh[j >> 1][(j & 1) * 2]);
#pragma unroll
            for (int a = 0; a < 2; a++)
#pragma unroll
                for (int j = 0; j < 8; j++)
                    mma16816(acc[a][j], afh[a], &bl[j >> 1][(j & 1) * 2]);
#pragma unroll
            for (int a = 0; a < 2; a++)
#pragma unroll
                for (int j = 0; j < 8; j++)
                    mma16816(acc[a][j], afl[a], &bh[j >> 1][(j & 1) * 2]);
        }

        __syncthreads();
        if (kc + 2 < 8) fill(b, kc + 2);
    }

    // epilogue: add bias, store natural layout (coalesced float2)
#pragma unroll
    for (int j = 0; j < 8; j++) {
        const int col = n0 + ng * 64 + j * 8 + (lane & 3) * 2;
        const float2 bv = *(const float2*)(bias + col);
#pragma unroll
        for (int a = 0; a < 2; a++) {
            const int r0 = m0 + mg * 32 + a * 16 + (lane >> 2);
            float2 o0, o1;
            o0.x = acc[a][j][0] + bv.x;
            o0.y = acc[a][j][1] + bv.y;
            o1.x = acc[a][j][2] + bv.x;
            o1.y = acc[a][j][3] + bv.y;
            *(float2*)&g_xW[dir][r0][col]     = o0;
            *(float2*)&g_xW[dir][r0 + 8][col] = o1;
        }
    }
}

// ---------------- persistent HMMA recurrence (unchanged from round 8) -------
__device__ __forceinline__ float sigmoidf_(float v) { return 1.0f / (1.0f + expf(-v)); }

__global__ void __launch_bounds__(256, 1)
rec_kernel(const int* __restrict__ x, float* __restrict__ out)
{
    extern __shared__ __align__(1024) char smem[];
    const uint32_t sb = s2u(smem);

    const int tid  = threadIdx.x;
    const int wid  = tid >> 5;
    const int lane = tid & 31;
    const int bid  = blockIdx.x;
    const int dir  = bid >> 6;
    const int mt   = (bid >> 5) & 1;
    const int nt   = bid & 31;
    const int grp  = bid >> 5;
    const int m0   = mt * 128;
    const int wb   = wid * 16;

    for (int i = tid; i < 8192; i += 256) {
        int prec = i >> 12;
        int kc   = (i >> 9) & 7;
        int P    = (i >> 3) & 63;
        int seg  = i & 7;
        const void* src = &g_Upk[prec][dir][nt * 64 + P][kc * 64 + seg * 8];
        uint32_t dst = sb + SM_B + (uint32_t)(prec * 8 + kc) * 8192
                     + SWZ((uint32_t)(P * 128 + seg * 16));
        cpasync16(dst, src);
    }
    cpcommit();

    float c_reg[8], h_reg[8];
#pragma unroll
    for (int s = 0; s < 8; s++) { c_reg[s] = 0.0f; h_reg[s] = 0.0f; }
    unsigned barcnt = 0;

    auto fillA = [&](int b, int kc, int pin) {
#pragma unroll
        for (int j = 0; j < 8; j++) {
            int i    = tid + j * 256;
            int prec = i >> 10;
            int r    = (i >> 3) & 127;
            int seg  = i & 7;
            const void* src = &g_hsp[prec][dir][pin][m0 + r][kc * 64 + seg * 8];
            uint32_t dst = sb + SM_A + (uint32_t)b * 32768 + (uint32_t)prec * 16384
                         + SWZ((uint32_t)(r * 128 + seg * 16));
            cpasync16(dst, src);
        }
        cpcommit();
    };

    auto gbar = [&]() {
        __threadfence();
        __syncthreads();
        barcnt++;
        if (tid == 0) {
            atomicAdd(&g_bar4[grp], 1u);
            const unsigned target = barcnt * 32;
            while (*(volatile unsigned*)&g_bar4[grp] < target) __nanosleep(32);
        }
        __syncthreads();
        __threadfence();
    };

    const int rA = lane >> 2;
    const int cq = lane & 3;

    for (int t = 0; t < T_LEN; t++) {
        const int pin  = t & 1;
        const int pout = pin ^ 1;
        const int tt   = dir ? (T_LEN - 1 - t) : t;

        const int n0r   = m0 + wb + rA;
        const int row0  = n0r * T_LEN + tt;
        const int row1  = (n0r + 8) * T_LEN + tt;
        const int msk0  = x[row0];
        const int msk1  = x[row1];
        float xwv[2][4][4];
#pragma unroll
        for (int rh = 0; rh < 2; rh++) {
            const float* base = &g_xW[dir][rh ? row1 : row0][nt * 16 + cq];
#pragma unroll
            for (int uu = 0; uu < 4; uu++)
#pragma unroll
                for (int g = 0; g < 4; g++)
                    xwv[rh][uu][g] = base[g * UNITS + uu * 4];
        }

        float acc[8][4];
#pragma unroll
        for (int j = 0; j < 8; j++)
#pragma unroll
            for (int c = 0; c < 4; c++) acc[j][c] = 0.0f;

        fillA(0, 0, pin);
        fillA(1, 1, pin);
        fillA(2, 2, pin);

        for (int kc = 0; kc < 8; kc++) {
            if (kc < 6) cpwait<2>();
            else if (kc == 6) cpwait<1>();
            else cpwait<0>();
            __syncthreads();

            const uint32_t aHi = sb + SM_A + (uint32_t)(kc % 3) * 32768;
            const uint32_t aLo = aHi + 16384;
            const uint32_t bHi = sb + SM_B + (uint32_t)kc * 8192;
            const uint32_t bLo = bHi + 65536u;

#pragma unroll
            for (int kk = 0; kk < 4; kk++) {
                const int kb = kk * 32;
                uint32_t afh[4], afl[4], bh[4][4], bl[4][4];
                ldA16(afh, aHi, wb, kb, lane);
                ldA16(afl, aLo, wb, kb, lane);
#pragma unroll
                for (int p4 = 0; p4 < 4; p4++) {
                    ldB16(bh[p4], bHi, p4 * 16, kb, lane);
                    ldB16(bl[p4], bLo, p4 * 16, kb, lane);
                }
#pragma unroll
                for (int j = 0; j < 8; j++)
                    mma16816(acc[j], afh, &bh[j >> 1][(j & 1) * 2]);
#pragma unroll
                for (int j = 0; j < 8; j++)
                    mma16816(acc[j], afh, &bl[j >> 1][(j & 1) * 2]);
#pragma unroll
                for (int j = 0; j < 8; j++)
                    mma16816(acc[j], afl, &bh[j >> 1][(j & 1) * 2]);
            }

            __syncthreads();
            if (kc + 3 < 8) fillA(kc % 3, kc + 3, pin);
        }

#pragma unroll
        for (int rh = 0; rh < 2; rh++) {
            const int n    = n0r + rh * 8;
            const bool msk = (rh ? msk1 : msk0) != 0;
#pragma unroll
            for (int uu = 0; uu < 4; uu++) {
                const float zi = xwv[rh][uu][0] + acc[uu * 2 + 0][rh * 2 + 0];
                const float zf = xwv[rh][uu][1] + acc[uu * 2 + 0][rh * 2 + 1];
                const float zg = xwv[rh][uu][2] + acc[uu * 2 + 1][rh * 2 + 0];
                const float zo = xwv[rh][uu][3] + acc[uu * 2 + 1][rh * 2 + 1];
                const int s = rh * 4 + uu;
                float ig = sigmoidf_(zi), fg = sigmoidf_(zf);
                float gg = tanhf(zg),     og = sigmoidf_(zo);
                float cn = fmaf(fg, c_reg[s], ig * gg);
                float hn = og * tanhf(cn);
                if (!msk) { cn = c_reg[s]; hn = h_reg[s]; }
                c_reg[s] = cn;
                h_reg[s] = hn;
                const int gu = nt * 16 + uu * 4 + cq;
                __nv_bfloat16 hh = __float2bfloat16(hn);
                g_hsp[0][dir][pout][n][gu] = hh;
                g_hsp[1][dir][pout][n][gu] = __float2bfloat16(hn - __bfloat162float(hh));
            }
        }

        if (t < T_LEN - 1) gbar();
    }

#pragma unroll
    for (int rh = 0; rh < 2; rh++) {
        const int n = m0 + wb + rA + rh * 8;
#pragma unroll
        for (int uu = 0; uu < 4; uu++) {
            const int gu = nt * 16 + uu * 4 + cq;
            out[(size_t)n * 1024 + dir * 512 + gu] = h_reg[rh * 4 + uu];
        }
    }
}

// ---------------- launch ----------------------------------------------------
extern "C" void kernel_launch(void* const* d_in, const int* in_sizes, int n_in,
                              void* d_out, int out_size)
{
    const int*   x   = (const int*)  d_in[0];
    const float* emb = (const float*)d_in[1];
    const float* Wf  = (const float*)d_in[2];
    const float* Uf  = (const float*)d_in[3];
    const float* bf  = (const float*)d_in[4];
    const float* Wb  = (const float*)d_in[5];
    const float* Ub  = (const float*)d_in[6];
    const float* bb  = (const float*)d_in[7];
    float* out = (float*)d_out;
    (void)in_sizes; (void)n_in; (void)out_size;

    cudaFuncSetAttribute(rec_kernel,
                         cudaFuncAttributeMaxDynamicSharedMemorySize, SMEM_REC);
    cudaFuncSetAttribute(xw_hmma,
                         cudaFuncAttributeMaxDynamicSharedMemorySize, SMEM_XW);

    init_kernel<<<2048, 256>>>();
    upack_kernel<<<dim3(4096, 2), 256>>>(Uf, Ub);
    wpack_kernel<<<dim3(4096, 2), 256>>>(Wf, Wb);
    apack_kernel<<<M_ALL, 256>>>(x, emb);

    dim3 gx(16, 256, 2);
    xw_hmma<<<gx, 256, SMEM_XW>>>(bf, bb);

    rec_kernel<<<128, 256, SMEM_REC>>>(x, out);
}

// round 13
// speedup vs baseline: 4.8120x; 1.4049x over previous
#include <cuda_runtime.h>
#include <cuda_fp16.h>
#include <math.h>
#include <stdint.h>

#define N_SEQ   256
#define T_LEN   128
#define EMBED   512
#define UNITS   512
#define GATEC   2048
#define M_ALL   (N_SEQ * T_LEN)

// rec smem: B (U hi/lo) 128KB + A (h fp16) 3 x 16KB
#define SM_B     0
#define SM_A     131072
#define SMEM_REC (SM_A + 3 * 16384)      // 180224 B
// xw smem: 2 bufs x (A 16KB + Bhi 16KB + Blo 16KB)
#define XW_BUF   49152
#define SMEM_XW  (2 * XW_BUF)            // 98304 B

#define SWZ(o) ((o) ^ (((o) >> 3) & 0x70))

// ---------------- PTX helpers (plain-sm_103-legal only) ---------------------
__device__ __forceinline__ uint32_t s2u(const void* p) {
    uint32_t a;
    asm("{ .reg .u64 t; cvta.to.shared.u64 t, %1; cvt.u32.u64 %0, t; }"
        : "=r"(a) : "l"(p));
    return a;
}
__device__ __forceinline__ void cpasync16(uint32_t dst, const void* src) {
    asm volatile("cp.async.cg.shared.global [%0], [%1], 16;" :: "r"(dst), "l"(src));
}
__device__ __forceinline__ void cpcommit() { asm volatile("cp.async.commit_group;"); }
template <int N> __device__ __forceinline__ void cpwait() {
    asm volatile("cp.async.wait_group %0;" :: "n"(N));
}
__device__ __forceinline__ void ldsm4(uint32_t* r, uint32_t addr) {
    asm volatile("ldmatrix.sync.aligned.m8n8.x4.shared.b16 {%0,%1,%2,%3}, [%4];"
        : "=r"(r[0]), "=r"(r[1]), "=r"(r[2]), "=r"(r[3]) : "r"(addr));
}
__device__ __forceinline__ void mma16816(float* c, const uint32_t* a, const uint32_t* b) {
    asm volatile(
        "mma.sync.aligned.m16n8k16.row.col.f32.f16.f16.f32 "
        "{%0,%1,%2,%3}, {%4,%5,%6,%7}, {%8,%9}, {%0,%1,%2,%3};"
        : "+f"(c[0]), "+f"(c[1]), "+f"(c[2]), "+f"(c[3])
        : "r"(a[0]), "r"(a[1]), "r"(a[2]), "r"(a[3]), "r"(b[0]), "r"(b[1]));
}
// A fragment m16xk16 row-major: rows mb.., k-bytes kb within 128B rows
__device__ __forceinline__ void ldA16(uint32_t* r, uint32_t tile, int mb, int kb, int lane) {
    uint32_t o = (uint32_t)((mb + (lane & 15)) * 128 + kb + ((lane >> 4) << 4));
    ldsm4(r, tile + SWZ(o));
}
// B fragments: two n8 tiles (rows nb..nb+15 of [n][k] layout)
__device__ __forceinline__ void ldB16(uint32_t* r, uint32_t tile, int nb, int kb, int lane) {
    uint32_t o = (uint32_t)((nb + ((lane >> 4) << 3) + (lane & 7)) * 128 + kb
                            + (((lane >> 3) & 1) << 4));
    ldsm4(r, tile + SWZ(o));
}

// ---------------- scratch ---------------------------------------------------
__device__ float    g_xW[2][M_ALL][GATEC];        // natural layout x@W + b
__device__ __half   g_Upk[2][2][GATEC][UNITS];    // [prec][dir][packed n][k]
__device__ __half   g_Wpk[2][2][GATEC][EMBED];    // [prec][dir][n][k]
__device__ __half   g_Asp[M_ALL][EMBED];          // gathered emb fp16
__device__ __half   g_hsp[2][2][N_SEQ][UNITS];    // [dir][parity][n][u] fp16
__device__ unsigned g_barp[4 * 32];               // padded per-group barriers

// packed col p: j=p>>3, q=(p>>1)&3, e=p&1 -> unit=(j>>1)*4+q, gate=(j&1)*2+e

// ---------------- init ------------------------------------------------------
__global__ void init_kernel()
{
    int i = blockIdx.x * 256 + threadIdx.x;
    if (i < 128) g_barp[i] = 0;
    if (i < 2 * N_SEQ * UNITS) {
        int dir = i / (N_SEQ * UNITS);
        int off = i % (N_SEQ * UNITS);
        (&g_hsp[dir][0][0][0])[off] = __float2half(0.0f);
    }
}

// ---------------- U (permuted) + W pack: fp32 -> fp16 hi/lo -----------------
__global__ void pack_kernel(const float* __restrict__ Uf, const float* __restrict__ Ub,
                            const float* __restrict__ Wf, const float* __restrict__ Wb)
{
    int i     = blockIdx.x * 256 + threadIdx.x;   // over 2048*512
    int dir   = blockIdx.y;
    int which = blockIdx.z;                       // 0: U, 1: W
    if (i >= GATEC * 512) return;
    int P = i >> 9, k = i & 511;
    float v;
    if (which == 0) {
        int nt = P >> 6, p = P & 63;
        int j = p >> 3, q = (p >> 1) & 3, e = p & 1;
        int unit = nt * 16 + (j >> 1) * 4 + q;
        int gate = (j & 1) * 2 + e;
        const float* U = dir ? Ub : Uf;
        v = U[(size_t)k * GATEC + gate * UNITS + unit];
    } else {
        const float* W = dir ? Wb : Wf;
        v = W[(size_t)k * GATEC + P];
    }
    __half hi = __float2half(v);
    __half lo = __float2half(v - __half2float(hi));
    if (which == 0) { g_Upk[0][dir][P][k] = hi; g_Upk[1][dir][P][k] = lo; }
    else            { g_Wpk[0][dir][P][k] = hi; g_Wpk[1][dir][P][k] = lo; }
}

// ---------------- A pack: gather emb rows -> fp16 ---------------------------
__global__ void apack_kernel(const int* __restrict__ x, const float* __restrict__ emb)
{
    const int m  = blockIdx.x;
    const int k2 = threadIdx.x;                   // 0..255 pairs
    const int id = x[m];
    float2 v = *(const float2*)(emb + (size_t)id * EMBED + k2 * 2);
    *(__half2*)&g_Asp[m][k2 * 2] = __floats2half2_rn(v.x, v.y);
}

// ---------------- input projection via 2-pass fp16 HMMA ---------------------
__global__ void __launch_bounds__(256, 2)
xw_hmma(const float* __restrict__ bf_, const float* __restrict__ bb_)
{
    extern __shared__ __align__(1024) char smem[];
    const uint32_t sb = s2u(smem);

    const int tid  = threadIdx.x;
    const int wid  = tid >> 5;
    const int lane = tid & 31;
    const int nt   = blockIdx.x;                  // 0..15
    const int mt   = blockIdx.y;                  // 0..255
    const int dir  = blockIdx.z;
    const int m0   = mt * 128;
    const int n0   = nt * 128;
    const float* __restrict__ bias = dir ? bb_ : bf_;

    const int mg = wid & 3;                       // warp m-group (32 rows)
    const int ng = wid >> 2;                      // warp n-group (64 cols)

    auto fill = [&](int b, int kc) {
#pragma unroll
        for (int j = 0; j < 12; j++) {
            int i    = tid + j * 256;             // 0..3071
            int reg  = i >> 10;                   // 0:A 1:Bhi 2:Blo
            int idx  = i & 1023;
            int r    = idx >> 3;
            int seg  = idx & 7;
            const void* src = (reg == 0)
                ? (const void*)&g_Asp[m0 + r][kc * 64 + seg * 8]
                : (const void*)&g_Wpk[reg - 1][dir][n0 + r][kc * 64 + seg * 8];
            uint32_t dst = sb + (uint32_t)b * XW_BUF + (uint32_t)reg * 16384
                         + SWZ((uint32_t)(r * 128 + seg * 16));
            cpasync16(dst, src);
        }
        cpcommit();
    };

    float acc[2][8][4];
#pragma unroll
    for (int a = 0; a < 2; a++)
#pragma unroll
        for (int j = 0; j < 8; j++)
#pragma unroll
            for (int c = 0; c < 4; c++) acc[a][j][c] = 0.0f;

    fill(0, 0);
    fill(1, 1);

    for (int kc = 0; kc < 8; kc++) {
        const int b = kc & 1;
        if (kc < 7) cpwait<1>(); else cpwait<0>();
        __syncthreads();

        const uint32_t aT  = sb + (uint32_t)b * XW_BUF;
        const uint32_t bHi = aT + 16384;
        const uint32_t bLo = aT + 32768;

#pragma unroll
        for (int kk = 0; kk < 4; kk++) {
            const int kb = kk * 32;
            uint32_t af[2][4], bh[4][4], bl[4][4];
            ldA16(af[0], aT, mg * 32,      kb, lane);
            ldA16(af[1], aT, mg * 32 + 16, kb, lane);
#pragma unroll
            for (int p4 = 0; p4 < 4; p4++) {
                ldB16(bh[p4], bHi, ng * 64 + p4 * 16, kb, lane);
                ldB16(bl[p4], bLo, ng * 64 + p4 * 16, kb, lane);
            }
#pragma unroll
            for (int a = 0; a < 2; a++)
#pragma unroll
                for (int j = 0; j < 8; j++)
                    mma16816(acc[a][j], af[a], &bh[j >> 1][(j & 1) * 2]);
#pragma unroll
            for (int a = 0; a < 2; a++)
#pragma unroll
                for (int j = 0; j < 8; j++)
                    mma16816(acc[a][j], af[a], &bl[j >> 1][(j & 1) * 2]);
        }

        __syncthreads();
        if (kc + 2 < 8) fill(b, kc + 2);
    }

    // epilogue: add bias, store natural layout (coalesced float2)
#pragma unroll
    for (int j = 0; j < 8; j++) {
        const int col = n0 + ng * 64 + j * 8 + (lane & 3) * 2;
        const float2 bv = *(const float2*)(bias + col);
#pragma unroll
        for (int a = 0; a < 2; a++) {
            const int r0 = m0 + mg * 32 + a * 16 + (lane >> 2);
            float2 o0, o1;
            o0.x = acc[a][j][0] + bv.x;
            o0.y = acc[a][j][1] + bv.y;
            o1.x = acc[a][j][2] + bv.x;
            o1.y = acc[a][j][3] + bv.y;
            *(float2*)&g_xW[dir][r0][col]     = o0;
            *(float2*)&g_xW[dir][r0 + 8][col] = o1;
        }
    }
}

// ---------------- persistent 2-pass fp16 HMMA recurrence --------------------
__device__ __forceinline__ float sigmoidf_(float v) { return 1.0f / (1.0f + expf(-v)); }

__global__ void __launch_bounds__(256, 1)
rec_kernel(const int* __restrict__ x, float* __restrict__ out)
{
    extern __shared__ __align__(1024) char smem[];
    const uint32_t sb = s2u(smem);

    const int tid  = threadIdx.x;
    const int wid  = tid >> 5;
    const int lane = tid & 31;
    const int bid  = blockIdx.x;
    const int dir  = bid >> 6;
    const int mt   = (bid >> 5) & 1;
    const int nt   = bid & 31;
    const int grp  = bid >> 5;
    const int m0   = mt * 128;
    const int wb   = wid * 16;

    // ---- one-time B (U) preload: hi+lo, 8 K-chunks -------------------------
    for (int i = tid; i < 8192; i += 256) {
        int prec = i >> 12;
        int kc   = (i >> 9) & 7;
        int P    = (i >> 3) & 63;
        int seg  = i & 7;
        const void* src = &g_Upk[prec][dir][nt * 64 + P][kc * 64 + seg * 8];
        uint32_t dst = sb + SM_B + (uint32_t)(prec * 8 + kc) * 8192
                     + SWZ((uint32_t)(P * 128 + seg * 16));
        cpasync16(dst, src);
    }
    cpcommit();

    float c_reg[8], h_reg[8];
#pragma unroll
    for (int s = 0; s < 8; s++) { c_reg[s] = 0.0f; h_reg[s] = 0.0f; }
    unsigned barcnt = 0;

    auto fillA = [&](int b, int kc, int pin) {
#pragma unroll
        for (int j = 0; j < 4; j++) {
            int i   = tid + j * 256;              // 0..1023
            int r   = i >> 3;
            int seg = i & 7;
            const void* src = &g_hsp[dir][pin][m0 + r][kc * 64 + seg * 8];
            uint32_t dst = sb + SM_A + (uint32_t)b * 16384
                         + SWZ((uint32_t)(r * 128 + seg * 16));
            cpasync16(dst, src);
        }
        cpcommit();
    };

    auto gbar = [&]() {
        __syncthreads();
        barcnt++;
        if (tid == 0) {
            unsigned* ctr = &g_barp[grp * 32];
            const unsigned target = barcnt * 32;
            asm volatile("red.release.gpu.add.u32 [%0], 1;" :: "l"(ctr) : "memory");
            unsigned v;
            while (true) {
                asm volatile("ld.acquire.gpu.u32 %0, [%1];" : "=r"(v) : "l"(ctr) : "memory");
                if (v >= target) break;
                __nanosleep(32);
            }
        }
        __syncthreads();
    };

    const int rA = lane >> 2;
    const int cq = lane & 3;

    for (int t = 0; t < T_LEN; t++) {
        const int pin  = t & 1;
        const int pout = pin ^ 1;
        const int tt   = dir ? (T_LEN - 1 - t) : t;

        const int n0r   = m0 + wb + rA;
        const int row0  = n0r * T_LEN + tt;
        const int row1  = (n0r + 8) * T_LEN + tt;
        const int msk0  = x[row0];
        const int msk1  = x[row1];
        float xwv[2][4][4];
#pragma unroll
        for (int rh = 0; rh < 2; rh++) {
            const float* base = &g_xW[dir][rh ? row1 : row0][nt * 16 + cq];
#pragma unroll
            for (int uu = 0; uu < 4; uu++)
#pragma unroll
                for (int g = 0; g < 4; g++)
                    xwv[rh][uu][g] = base[g * UNITS + uu * 4];
        }

        float acc[8][4];
#pragma unroll
        for (int j = 0; j < 8; j++)
#pragma unroll
            for (int c = 0; c < 4; c++) acc[j][c] = 0.0f;

        fillA(0, 0, pin);
        fillA(1, 1, pin);
        fillA(2, 2, pin);

        for (int kc = 0; kc < 8; kc++) {
            if (kc < 6) cpwait<2>();
            else if (kc == 6) cpwait<1>();
            else cpwait<0>();
            __syncthreads();

            const uint32_t aT  = sb + SM_A + (uint32_t)(kc % 3) * 16384;
            const uint32_t bHi = sb + SM_B + (uint32_t)kc * 8192;
            const uint32_t bLo = bHi + 65536u;

#pragma unroll
            for (int kk = 0; kk < 4; kk++) {
                const int kb = kk * 32;
                uint32_t af[4], bh[4][4], bl[4][4];
                ldA16(af, aT, wb, kb, lane);
#pragma unroll
                for (int p4 = 0; p4 < 4; p4++) {
                    ldB16(bh[p4], bHi, p4 * 16, kb, lane);
                    ldB16(bl[p4], bLo, p4 * 16, kb, lane);
                }
#pragma unroll
                for (int j = 0; j < 8; j++)
                    mma16816(acc[j], af, &bh[j >> 1][(j & 1) * 2]);
#pragma unroll
                for (int j = 0; j < 8; j++)
                    mma16816(acc[j], af, &bl[j >> 1][(j & 1) * 2]);
            }

            __syncthreads();
            if (kc + 3 < 8) fillA(kc % 3, kc + 3, pin);
        }

        // ---- gate math + masked update; lane owns 2 rows x 4 units ---------
#pragma unroll
        for (int rh = 0; rh < 2; rh++) {
            const int n    = n0r + rh * 8;
            const bool msk = (rh ? msk1 : msk0) != 0;
#pragma unroll
            for (int uu = 0; uu < 4; uu++) {
                const float zi = xwv[rh][uu][0] + acc[uu * 2 + 0][rh * 2 + 0];
                const float zf = xwv[rh][uu][1] + acc[uu * 2 + 0][rh * 2 + 1];
                const float zg = xwv[rh][uu][2] + acc[uu * 2 + 1][rh * 2 + 0];
                const float zo = xwv[rh][uu][3] + acc[uu * 2 + 1][rh * 2 + 1];
                const int s = rh * 4 + uu;
                float ig = sigmoidf_(zi), fg = sigmoidf_(zf);
                float gg = tanhf(zg),     og = sigmoidf_(zo);
                float cn = fmaf(fg, c_reg[s], ig * gg);
                float hn = og * tanhf(cn);
                if (!msk) { cn = c_reg[s]; hn = h_reg[s]; }
                c_reg[s] = cn;
                h_reg[s] = hn;
                const int gu = nt * 16 + uu * 4 + cq;
                g_hsp[dir][pout][n][gu] = __float2half(hn);
            }
        }

        if (t < T_LEN - 1) gbar();
    }

    // ---- final output: concat(h_fwd, h_bwd), straight from registers -------
#pragma unroll
    for (int rh = 0; rh < 2; rh++) {
        const int n = m0 + wb + rA + rh * 8;
#pragma unroll
        for (int uu = 0; uu < 4; uu++) {
            const int gu = nt * 16 + uu * 4 + cq;
            out[(size_t)n * 1024 + dir * 512 + gu] = h_reg[rh * 4 + uu];
        }
    }
}

// ---------------- launch ----------------------------------------------------
extern "C" void kernel_launch(void* const* d_in, const int* in_sizes, int n_in,
                              void* d_out, int out_size)
{
    const int*   x   = (const int*)  d_in[0];
    const float* emb = (const float*)d_in[1];
    const float* Wf  = (const float*)d_in[2];
    const float* Uf  = (const float*)d_in[3];
    const float* bf  = (const float*)d_in[4];
    const float* Wb  = (const float*)d_in[5];
    const float* Ub  = (const float*)d_in[6];
    const float* bb  = (const float*)d_in[7];
    float* out = (float*)d_out;
    (void)in_sizes; (void)n_in; (void)out_size;

    cudaFuncSetAttribute(rec_kernel,
                         cudaFuncAttributeMaxDynamicSharedMemorySize, SMEM_REC);
    cudaFuncSetAttribute(xw_hmma,
                         cudaFuncAttributeMaxDynamicSharedMemorySize, SMEM_XW);

    init_kernel<<<1024, 256>>>();
    pack_kernel<<<dim3(4096, 2, 2), 256>>>(Uf, Ub, Wf, Wb);
    apack_kernel<<<M_ALL, 256>>>(x, emb);

    dim3 gx(16, 256, 2);
    xw_hmma<<<gx, 256, SMEM_XW>>>(bf, bb);

    rec_kernel<<<128, 256, SMEM_REC>>>(x, out);
}